// round 5
// baseline (speedup 1.0000x reference)
#include <cuda_runtime.h>

// ExtractLearnableSlices — warp-per-head, no block barrier.
//   x: (B=64, C=64, L=16384) f32
//   channel_params/offset_params: (128,) f32
//   out: (B=64, N=128, W=512) f32
//
// Each warp owns one (b, head): stages the fused channel lerp
// v[l] = xf[l] + wc*(xc[l]-xf[l]) over a 520-float window into its private
// smem segment (10 independent LDG.128 per lane in flight), __syncwarp, then
// 16 outputs/lane time-lerp. pos = t0 + j computed in f32 exactly as ref.

#define B_DIM   64
#define C_DIM   64
#define L_DIM   16384
#define N_HEADS 128
#define WIDTH   512

#define WARPS_PER_BLK 8
#define THREADS      (WARPS_PER_BLK * 32)
#define SMEM_F4      130            // float4 per head window (520 floats)
#define SMEM_FLOATS  (SMEM_F4 * 4)

__global__ __launch_bounds__(THREADS) void extract_slices_kernel(
    const float* __restrict__ x,
    const float* __restrict__ channel_params,
    const float* __restrict__ offset_params,
    float* __restrict__ out)
{
    __shared__ float v[WARPS_PER_BLK][SMEM_FLOATS];

    const int w    = threadIdx.x >> 5;            // warp 0..7
    const int lane = threadIdx.x & 31;
    const int i    = blockIdx.x * WARPS_PER_BLK + w;  // head 0..127
    const int b    = blockIdx.y;                      // batch 0..63

    // ---- per-head uniform params ----
    const float cp = __ldg(&channel_params[i]);
    const float op = __ldg(&offset_params[i]);

    const float sc      = 1.0f / (1.0f + expf(-cp));
    const float desired = sc * (float)(C_DIM - 1);   // > 0
    const int   fc      = (int)desired;              // == floor (positive)
    const int   cc      = min(fc + 1, C_DIM - 1);
    const float wc      = desired - (float)fc;

    const float so  = 1.0f / (1.0f + expf(-op));
    const float t0  = so * (float)(L_DIM - WIDTH);   // > 0
    const int   pf0 = (int)t0;                       // == floor (positive)
    const int   l0  = (pf0 - 1) & ~3;                // float4-aligned, slack below

    const float* __restrict__ xb  = x + (size_t)b * (size_t)(C_DIM * L_DIM);
    const float4* __restrict__ xf4 = (const float4*)(xb + fc * L_DIM + l0);
    const float4* __restrict__ xc4 = (const float4*)(xb + cc * L_DIM + l0);
    float4* __restrict__ v4 = (float4*)v[w];

    // ---- stage: 130 float4 across 32 lanes; all LDGs independent ----
    float4 a[5], c[5];
    #pragma unroll
    for (int k = 0; k < 4; ++k) {
        a[k] = xf4[lane + k * 32];
        c[k] = xc4[lane + k * 32];
    }
    const bool tail = (lane < 2);
    if (tail) { a[4] = xf4[lane + 128]; c[4] = xc4[lane + 128]; }

    #pragma unroll
    for (int k = 0; k < 4; ++k) {
        float4 r;
        r.x = a[k].x + wc * (c[k].x - a[k].x);
        r.y = a[k].y + wc * (c[k].y - a[k].y);
        r.z = a[k].z + wc * (c[k].z - a[k].z);
        r.w = a[k].w + wc * (c[k].w - a[k].w);
        v4[lane + k * 32] = r;
    }
    if (tail) {
        float4 r;
        r.x = a[4].x + wc * (c[4].x - a[4].x);
        r.y = a[4].y + wc * (c[4].y - a[4].y);
        r.z = a[4].z + wc * (c[4].z - a[4].z);
        r.w = a[4].w + wc * (c[4].w - a[4].w);
        v4[lane + 128] = r;
    }
    __syncwarp();

    // ---- epilogue: 16 outputs/lane, coalesced STG, conflict-free LDS ----
    const float* __restrict__ vh = v[w];
    float* __restrict__ orow = out + ((size_t)b * N_HEADS + i) * WIDTH + lane;

    #pragma unroll
    for (int k = 0; k < 16; ++k) {
        const float pos = t0 + (float)(lane + k * 32);  // exact ref f32 math
        const int   pf  = (int)pos;                     // floor (positive)
        const float wt  = pos - (float)pf;
        const int   idx = pf - l0;                      // in [0, 517]
        const float v0  = vh[idx];
        const float v1  = vh[idx + 1];
        orow[k * 32] = v0 + wt * (v1 - v0);
    }
}

extern "C" void kernel_launch(void* const* d_in, const int* in_sizes, int n_in,
                              void* d_out, int out_size)
{
    const float* x  = (const float*)d_in[0];
    const float* ch = (const float*)d_in[1];
    const float* of = (const float*)d_in[2];
    float* out = (float*)d_out;

    dim3 grid(N_HEADS / WARPS_PER_BLK, B_DIM);
    extract_slices_kernel<<<grid, THREADS>>>(x, ch, of, out);
}